// round 12
// baseline (speedup 1.0000x reference)
#include <cuda_runtime.h>
#include <math.h>

#define HIDDEN        2048
#define NUM_HEADS     16
#define HEAD_DIM      128
#define BLOCK_SZ      64
#define NUM_SEQS      64
#define MAX_SEQ_LEN   2048
#define MAX_BLOCKS    32
#define NUM_KV_BLOCKS 2048
#define SCALE_F       0.088388347648318447f   // 128^-0.5

#define KCHUNKS       16                       // GEMM split-K chunks
#define KCHUNK_SZ     (HIDDEN / KCHUNKS)       // 128
#define SPLITS        8                        // split-KV
#define CHUNK_MAX     (MAX_SEQ_LEN / SPLITS)   // 256

// GEMM tile: 64 seqs x 128 cols x 128 k per CTA; W pipelined in 32-row stages
#define APAD          132                      // fp32 row pitch (128 + 4)
#define WROWS         32                       // rows per W stage
#define GEMM_SMEM_BYTES ((64 * APAD + 2 * WROWS * APAD) * 4)   // 67584

// ---- static scratch (no allocations allowed) ----
__device__ float  g_q[NUM_SEQS * HIDDEN];
__device__ float  g_attn[NUM_SEQS * HIDDEN];
__device__ float  g_part[KCHUNKS * NUM_SEQS * HIDDEN];
__device__ float  g_po[NUM_SEQS * NUM_HEADS * SPLITS * HEAD_DIM];
__device__ float2 g_pml[NUM_SEQS * NUM_HEADS * SPLITS];

// ---- tf32 / cp.async helpers ----
__device__ __forceinline__ unsigned f2tf(float f) {
    unsigned r;
    asm("cvt.rna.tf32.f32 %0, %1;" : "=r"(r) : "f"(f));
    return r;
}
__device__ __forceinline__ void mma_tf32(float4& c,
                                         unsigned a0, unsigned a1, unsigned a2, unsigned a3,
                                         unsigned b0, unsigned b1) {
    asm("mma.sync.aligned.m16n8k8.row.col.f32.tf32.tf32.f32 "
        "{%0,%1,%2,%3}, {%4,%5,%6,%7}, {%8,%9}, {%0,%1,%2,%3};"
        : "+f"(c.x), "+f"(c.y), "+f"(c.z), "+f"(c.w)
        : "r"(a0), "r"(a1), "r"(a2), "r"(a3), "r"(b0), "r"(b1));
}
__device__ __forceinline__ unsigned smem_u32(const void* p) {
    return (unsigned)__cvta_generic_to_shared(p);
}
__device__ __forceinline__ void cp_async16(unsigned dst, const void* src) {
    asm volatile("cp.async.cg.shared.global [%0], [%1], 16;" :: "r"(dst), "l"(src));
}
#define CP_COMMIT()   asm volatile("cp.async.commit_group;" ::: "memory")
#define CP_WAIT(n)    asm volatile("cp.async.wait_group %0;" :: "n"(n) : "memory")

// ---------------------------------------------------------------------------
// Tensor-core split-K GEMM (tf32, cp.async pipelined) — unchanged from R10.
// ---------------------------------------------------------------------------
__global__ __launch_bounds__(256)
void gemm_tc_kernel(const float* __restrict__ A,
                    const float* __restrict__ W, int ldw,
                    float* __restrict__ part) {
    extern __shared__ float smemf[];
    float* Af = smemf;                     // [64][APAD]
    float* Wf = smemf + 64 * APAD;         // [2][WROWS][APAD]

    const int tid  = threadIdx.x;
    const int warp = tid >> 5;
    const int lane = tid & 31;
    const int r    = lane >> 2;
    const int qd   = lane & 3;
    const int wm   = warp >> 1;
    const int wn   = warp & 1;

    const int colbase = blockIdx.x * 128;
    const int kc      = blockIdx.y;
    const int kbeg    = kc * KCHUNK_SZ;

    const int a_row = tid >> 5, a_c4 = tid & 31;
    const int w_row = tid >> 5, w_c4 = tid & 31;

#pragma unroll
    for (int l = 0; l < 8; l++)
        cp_async16(smem_u32(&Af[(a_row + l * 8) * APAD + a_c4 * 4]),
                   &A[(size_t)(a_row + l * 8) * HIDDEN + kbeg + a_c4 * 4]);
#pragma unroll
    for (int l = 0; l < 4; l++)
        cp_async16(smem_u32(&Wf[(w_row + l * 8) * APAD + w_c4 * 4]),
                   &W[(size_t)(kbeg + w_row + l * 8) * ldw + colbase + w_c4 * 4]);
    CP_COMMIT();                                        // G0: A + W0
#pragma unroll
    for (int l = 0; l < 4; l++)
        cp_async16(smem_u32(&Wf[(WROWS + w_row + l * 8) * APAD + w_c4 * 4]),
                   &W[(size_t)(kbeg + WROWS + w_row + l * 8) * ldw + colbase + w_c4 * 4]);
    CP_COMMIT();                                        // G1: W1

    float4 c[8];
#pragma unroll
    for (int j = 0; j < 8; j++) c[j] = make_float4(0.f, 0.f, 0.f, 0.f);

    const float* arow0 = &Af[(wm * 16 + r) * APAD];
    const float* arow1 = &Af[(wm * 16 + r + 8) * APAD];
    const int nbase = wn * 64 + r;

#pragma unroll
    for (int kt = 0; kt < 4; kt++) {
        if (kt < 3) CP_WAIT(1); else CP_WAIT(0);
        __syncthreads();

        const float* wbuf = &Wf[(kt & 1) * WROWS * APAD];
        const int kofs = kt * WROWS;
#pragma unroll
        for (int ks = 0; ks < WROWS; ks += 8) {
            const unsigned a0 = f2tf(arow0[kofs + ks + qd]);
            const unsigned a1 = f2tf(arow1[kofs + ks + qd]);
            const unsigned a2 = f2tf(arow0[kofs + ks + qd + 4]);
            const unsigned a3 = f2tf(arow1[kofs + ks + qd + 4]);
            const float* w0 = &wbuf[(ks + qd) * APAD + nbase];
            const float* w1 = &wbuf[(ks + qd + 4) * APAD + nbase];
#pragma unroll
            for (int j = 0; j < 8; j++)
                mma_tf32(c[j], a0, a1, a2, a3, f2tf(w0[j * 8]), f2tf(w1[j * 8]));
        }

        if (kt + 2 < 4) {
            __syncthreads();
            const int s = kt + 2;
#pragma unroll
            for (int l = 0; l < 4; l++)
                cp_async16(smem_u32(&Wf[((kt & 1) * WROWS + w_row + l * 8) * APAD + w_c4 * 4]),
                           &W[(size_t)(kbeg + s * WROWS + w_row + l * 8) * ldw
                              + colbase + w_c4 * 4]);
            CP_COMMIT();
        }
    }

    const int row0 = wm * 16 + r;
#pragma unroll
    for (int j = 0; j < 8; j++) {
        const int col = colbase + wn * 64 + j * 8 + 2 * qd;
        *(float2*)&part[((size_t)kc * NUM_SEQS + row0) * HIDDEN + col] =
            make_float2(c[j].x, c[j].y);
        *(float2*)&part[((size_t)kc * NUM_SEQS + row0 + 8) * HIDDEN + col] =
            make_float2(c[j].z, c[j].w);
    }
}

// Reduce split-K partials + bias -> C[64, 2048]
__global__ __launch_bounds__(256)
void gemm_reduce_kernel(const float* __restrict__ part,
                        const float* __restrict__ bias,
                        float* __restrict__ C) {
    const int i = blockIdx.x * 256 + threadIdx.x;
    if (i >= NUM_SEQS * HIDDEN / 4) return;
    const int col4 = (i * 4) & (HIDDEN - 1);
    float4 s = *(const float4*)&bias[col4];
#pragma unroll
    for (int c = 0; c < KCHUNKS; c++) {
        const float4 p = *(const float4*)&part[(size_t)c * NUM_SEQS * HIDDEN + (size_t)i * 4];
        s.x += p.x; s.y += p.y; s.z += p.z; s.w += p.w;
    }
    *(float4*)&C[(size_t)i * 4] = s;
}

// ---------------------------------------------------------------------------
// Split-KV paged attention, partial pass. 8-deep token unroll per warp:
// 8 independent 512B K/V line loads in flight before the shuffle chains.
// ---------------------------------------------------------------------------
__global__ __launch_bounds__(128)
void attn_partial_kernel(const float* __restrict__ q,
                         const float* __restrict__ kv,
                         const int*   __restrict__ block_tables,
                         const int*   __restrict__ seq_lens,
                         float*  __restrict__ part_o,
                         float2* __restrict__ part_ml) {
    const int seq   = blockIdx.x;
    const int head  = blockIdx.y;
    const int split = blockIdx.z;
    const int tid   = threadIdx.x;
    const int warp  = tid >> 5;
    const int lane  = tid & 31;
    const int pidx  = (seq * NUM_HEADS + head) * SPLITS + split;

    __shared__ float s_scores[CHUNK_MAX];
    __shared__ int   s_bt[MAX_BLOCKS];
    __shared__ float s_red[4];
    __shared__ float s_acc[4][HEAD_DIM];

    const int sl    = seq_lens[seq];
    const int chunk = (sl + SPLITS - 1) / SPLITS;
    const int t0    = split * chunk;
    const int t1    = min(sl, t0 + chunk);
    const int n     = t1 - t0;

    if (n <= 0) {
        part_o[(size_t)pidx * HEAD_DIM + tid] = 0.0f;
        if (tid == 0) part_ml[pidx] = make_float2(-1e30f, 0.0f);
        return;
    }

    if (tid < MAX_BLOCKS)
        s_bt[tid] = block_tables[seq * MAX_BLOCKS + tid];
    __syncthreads();

    const float* K = kv;
    const float* V = kv + (size_t)NUM_KV_BLOCKS * BLOCK_SZ * HIDDEN;
    const size_t hoff = (size_t)head * HEAD_DIM + lane * 4;

    const float4 qf = *(const float4*)(q + (size_t)seq * HIDDEN + head * HEAD_DIM + lane * 4);

    // ---- Pass 1: scores, 8 tokens per warp per iteration ----
    float wmax = -1e30f;
    for (int tb = t0 + warp * 8; tb < t1; tb += 32) {
        float4 kf[8];
#pragma unroll
        for (int u = 0; u < 8; u++) {
            const int t = tb + u;
            if (t < t1) {
                const int phys = s_bt[t >> 6];
                kf[u] = *(const float4*)(K + ((size_t)phys * BLOCK_SZ + (t & 63)) * HIDDEN + hoff);
            } else {
                kf[u] = make_float4(0.f, 0.f, 0.f, 0.f);
            }
        }
        float d[8];
#pragma unroll
        for (int u = 0; u < 8; u++)
            d[u] = kf[u].x * qf.x + kf[u].y * qf.y + kf[u].z * qf.z + kf[u].w * qf.w;
#pragma unroll
        for (int o = 16; o; o >>= 1) {
#pragma unroll
            for (int u = 0; u < 8; u++)
                d[u] += __shfl_xor_sync(0xffffffffu, d[u], o);
        }
#pragma unroll
        for (int u = 0; u < 8; u++) {
            d[u] *= SCALE_F;
            if (tb + u < t1) {
                if (lane == 0) s_scores[tb + u - t0] = d[u];
                wmax = fmaxf(wmax, d[u]);
            }
        }
    }
    if (lane == 0) s_red[warp] = wmax;
    __syncthreads();
    const float m = fmaxf(fmaxf(s_red[0], s_red[1]), fmaxf(s_red[2], s_red[3]));
    __syncthreads();

    // ---- Pass 2: exp + sum ----
    float lsum = 0.0f;
    for (int i = tid; i < n; i += 128) {
        float p = __expf(s_scores[i] - m);
        s_scores[i] = p;
        lsum += p;
    }
#pragma unroll
    for (int o = 16; o; o >>= 1)
        lsum += __shfl_xor_sync(0xffffffffu, lsum, o);
    if (lane == 0) s_red[warp] = lsum;
    __syncthreads();
    const float ltot = s_red[0] + s_red[1] + s_red[2] + s_red[3];

    // ---- Pass 3: weighted V, 8 tokens per warp per iteration ----
    float4 acc = make_float4(0.f, 0.f, 0.f, 0.f);
    for (int tb = t0 + warp * 8; tb < t1; tb += 32) {
        float4 vf[8];
        float  p[8];
#pragma unroll
        for (int u = 0; u < 8; u++) {
            const int t = tb + u;
            if (t < t1) {
                const int phys = s_bt[t >> 6];
                vf[u] = *(const float4*)(V + ((size_t)phys * BLOCK_SZ + (t & 63)) * HIDDEN + hoff);
                p[u]  = s_scores[t - t0];
            } else {
                vf[u] = make_float4(0.f, 0.f, 0.f, 0.f);
                p[u]  = 0.0f;
            }
        }
#pragma unroll
        for (int u = 0; u < 8; u++) {
            acc.x = fmaf(p[u], vf[u].x, acc.x);
            acc.y = fmaf(p[u], vf[u].y, acc.y);
            acc.z = fmaf(p[u], vf[u].z, acc.z);
            acc.w = fmaf(p[u], vf[u].w, acc.w);
        }
    }
    *(float4*)&s_acc[warp][lane * 4] = acc;
    __syncthreads();

    part_o[(size_t)pidx * HEAD_DIM + tid] =
        s_acc[0][tid] + s_acc[1][tid] + s_acc[2][tid] + s_acc[3][tid];
    if (tid == 0) part_ml[pidx] = make_float2(m, ltot);
}

// Combine SPLITS partials via log-sum-exp. grid (64*16), 128 threads.
__global__ __launch_bounds__(128)
void attn_combine_kernel(const float*  __restrict__ part_o,
                         const float2* __restrict__ part_ml,
                         float* __restrict__ out) {
    const int sh  = blockIdx.x;
    const int tid = threadIdx.x;

    float2 ml[SPLITS];
#pragma unroll
    for (int i = 0; i < SPLITS; i++) ml[i] = part_ml[sh * SPLITS + i];

    float M = -1e30f;
#pragma unroll
    for (int i = 0; i < SPLITS; i++) M = fmaxf(M, ml[i].x);

    float L = 0.0f, o = 0.0f;
#pragma unroll
    for (int i = 0; i < SPLITS; i++) {
        const float w = __expf(ml[i].x - M);
        L += w * ml[i].y;
        o = fmaf(w, part_o[(size_t)(sh * SPLITS + i) * HEAD_DIM + tid], o);
    }

    const int seq = sh >> 4, head = sh & 15;
    out[(size_t)seq * HIDDEN + head * HEAD_DIM + tid] = o / L;
}

// ---------------------------------------------------------------------------
extern "C" void kernel_launch(void* const* d_in, const int* in_sizes, int n_in,
                              void* d_out, int out_size) {
    const float* hs     = (const float*)d_in[0];
    const float* kv     = (const float*)d_in[1];
    const float* W_attn = (const float*)d_in[2];
    const float* b_attn = (const float*)d_in[3];
    const float* W_proj = (const float*)d_in[4];
    const float* b_proj = (const float*)d_in[5];
    const int*   bt     = (const int*)d_in[6];
    const int*   slen   = (const int*)d_in[7];
    float*       out    = (float*)d_out;

    float  *qp = nullptr, *ap = nullptr, *pp = nullptr, *po = nullptr;
    float2 *pml = nullptr;
    cudaGetSymbolAddress((void**)&qp,  g_q);
    cudaGetSymbolAddress((void**)&ap,  g_attn);
    cudaGetSymbolAddress((void**)&pp,  g_part);
    cudaGetSymbolAddress((void**)&po,  g_po);
    cudaGetSymbolAddress((void**)&pml, g_pml);

    cudaFuncSetAttribute(gemm_tc_kernel,
                         cudaFuncAttributeMaxDynamicSharedMemorySize,
                         GEMM_SMEM_BYTES);

    const dim3 gemm_grid(HIDDEN / 128, KCHUNKS);
    const int  red_ctas = (NUM_SEQS * HIDDEN / 4 + 255) / 256;

    // Q projection (only first HIDDEN cols of W_attn are used)
    gemm_tc_kernel<<<gemm_grid, 256, GEMM_SMEM_BYTES>>>(hs, W_attn, 3 * HIDDEN, pp);
    gemm_reduce_kernel<<<red_ctas, 256>>>(pp, b_attn, qp);

    // Paged attention, split-KV
    attn_partial_kernel<<<dim3(NUM_SEQS, NUM_HEADS, SPLITS), 128>>>(qp, kv, bt, slen, po, pml);
    attn_combine_kernel<<<NUM_SEQS * NUM_HEADS, 128>>>(po, pml, ap);

    // Output projection
    gemm_tc_kernel<<<gemm_grid, 256, GEMM_SMEM_BYTES>>>(ap, W_proj, HIDDEN, pp);
    gemm_reduce_kernel<<<red_ctas, 256>>>(pp, b_proj, out);
}

// round 13
// speedup vs baseline: 1.1249x; 1.1249x over previous
#include <cuda_runtime.h>
#include <math.h>

#define HIDDEN        2048
#define NUM_HEADS     16
#define HEAD_DIM      128
#define BLOCK_SZ      64
#define NUM_SEQS      64
#define MAX_SEQ_LEN   2048
#define MAX_BLOCKS    32
#define NUM_KV_BLOCKS 2048
#define SCALE_F       0.088388347648318447f   // 128^-0.5

#define KCHUNKS       16                       // GEMM split-K chunks
#define KCHUNK_SZ     (HIDDEN / KCHUNKS)       // 128
#define SPLITS        8                        // split-KV
#define CHUNK_MAX     (MAX_SEQ_LEN / SPLITS)   // 256

// GEMM tile: 64 seqs x 128 cols x 128 k per CTA; W pipelined in 32-row stages
#define APAD          132                      // fp32 row pitch (128 + 4)
#define WROWS         32                       // rows per W stage
#define GEMM_SMEM_BYTES ((64 * APAD + 2 * WROWS * APAD) * 4)   // 67584

// ---- static scratch (no allocations allowed) ----
__device__ float  g_q[NUM_SEQS * HIDDEN];
__device__ float  g_attn[NUM_SEQS * HIDDEN];
__device__ float  g_part[KCHUNKS * NUM_SEQS * HIDDEN];
__device__ float  g_po[NUM_SEQS * NUM_HEADS * SPLITS * HEAD_DIM];
__device__ float2 g_pml[NUM_SEQS * NUM_HEADS * SPLITS];

// ---- tf32 / cp.async helpers ----
__device__ __forceinline__ unsigned f2tf(float f) {
    unsigned r;
    asm("cvt.rna.tf32.f32 %0, %1;" : "=r"(r) : "f"(f));
    return r;
}
__device__ __forceinline__ void mma_tf32(float4& c,
                                         unsigned a0, unsigned a1, unsigned a2, unsigned a3,
                                         unsigned b0, unsigned b1) {
    asm("mma.sync.aligned.m16n8k8.row.col.f32.tf32.tf32.f32 "
        "{%0,%1,%2,%3}, {%4,%5,%6,%7}, {%8,%9}, {%0,%1,%2,%3};"
        : "+f"(c.x), "+f"(c.y), "+f"(c.z), "+f"(c.w)
        : "r"(a0), "r"(a1), "r"(a2), "r"(a3), "r"(b0), "r"(b1));
}
__device__ __forceinline__ unsigned smem_u32(const void* p) {
    return (unsigned)__cvta_generic_to_shared(p);
}
__device__ __forceinline__ void cp_async16(unsigned dst, const void* src) {
    asm volatile("cp.async.cg.shared.global [%0], [%1], 16;" :: "r"(dst), "l"(src));
}
#define CP_COMMIT()   asm volatile("cp.async.commit_group;" ::: "memory")
#define CP_WAIT(n)    asm volatile("cp.async.wait_group %0;" :: "n"(n) : "memory")

// streaming (evict-first) float4 load for the single-use KV stream
__device__ __forceinline__ float4 ldcs4(const float* p) {
    float4 v;
    asm("ld.global.cs.v4.f32 {%0,%1,%2,%3}, [%4];"
        : "=f"(v.x), "=f"(v.y), "=f"(v.z), "=f"(v.w) : "l"(p));
    return v;
}

// ---------------------------------------------------------------------------
// Tensor-core split-K GEMM (tf32, cp.async pipelined) — proven R10 version.
// ---------------------------------------------------------------------------
__global__ __launch_bounds__(256)
void gemm_tc_kernel(const float* __restrict__ A,
                    const float* __restrict__ W, int ldw,
                    float* __restrict__ part) {
    extern __shared__ float smemf[];
    float* Af = smemf;                     // [64][APAD]
    float* Wf = smemf + 64 * APAD;         // [2][WROWS][APAD]

    const int tid  = threadIdx.x;
    const int warp = tid >> 5;
    const int lane = tid & 31;
    const int r    = lane >> 2;
    const int qd   = lane & 3;
    const int wm   = warp >> 1;
    const int wn   = warp & 1;

    const int colbase = blockIdx.x * 128;
    const int kc      = blockIdx.y;
    const int kbeg    = kc * KCHUNK_SZ;

    const int a_row = tid >> 5, a_c4 = tid & 31;
    const int w_row = tid >> 5, w_c4 = tid & 31;

#pragma unroll
    for (int l = 0; l < 8; l++)
        cp_async16(smem_u32(&Af[(a_row + l * 8) * APAD + a_c4 * 4]),
                   &A[(size_t)(a_row + l * 8) * HIDDEN + kbeg + a_c4 * 4]);
#pragma unroll
    for (int l = 0; l < 4; l++)
        cp_async16(smem_u32(&Wf[(w_row + l * 8) * APAD + w_c4 * 4]),
                   &W[(size_t)(kbeg + w_row + l * 8) * ldw + colbase + w_c4 * 4]);
    CP_COMMIT();                                        // G0: A + W0
#pragma unroll
    for (int l = 0; l < 4; l++)
        cp_async16(smem_u32(&Wf[(WROWS + w_row + l * 8) * APAD + w_c4 * 4]),
                   &W[(size_t)(kbeg + WROWS + w_row + l * 8) * ldw + colbase + w_c4 * 4]);
    CP_COMMIT();                                        // G1: W1

    float4 c[8];
#pragma unroll
    for (int j = 0; j < 8; j++) c[j] = make_float4(0.f, 0.f, 0.f, 0.f);

    const float* arow0 = &Af[(wm * 16 + r) * APAD];
    const float* arow1 = &Af[(wm * 16 + r + 8) * APAD];
    const int nbase = wn * 64 + r;

#pragma unroll
    for (int kt = 0; kt < 4; kt++) {
        if (kt < 3) CP_WAIT(1); else CP_WAIT(0);
        __syncthreads();

        const float* wbuf = &Wf[(kt & 1) * WROWS * APAD];
        const int kofs = kt * WROWS;
#pragma unroll
        for (int ks = 0; ks < WROWS; ks += 8) {
            const unsigned a0 = f2tf(arow0[kofs + ks + qd]);
            const unsigned a1 = f2tf(arow1[kofs + ks + qd]);
            const unsigned a2 = f2tf(arow0[kofs + ks + qd + 4]);
            const unsigned a3 = f2tf(arow1[kofs + ks + qd + 4]);
            const float* w0 = &wbuf[(ks + qd) * APAD + nbase];
            const float* w1 = &wbuf[(ks + qd + 4) * APAD + nbase];
#pragma unroll
            for (int j = 0; j < 8; j++)
                mma_tf32(c[j], a0, a1, a2, a3, f2tf(w0[j * 8]), f2tf(w1[j * 8]));
        }

        if (kt + 2 < 4) {
            __syncthreads();
            const int s = kt + 2;
#pragma unroll
            for (int l = 0; l < 4; l++)
                cp_async16(smem_u32(&Wf[((kt & 1) * WROWS + w_row + l * 8) * APAD + w_c4 * 4]),
                           &W[(size_t)(kbeg + s * WROWS + w_row + l * 8) * ldw
                              + colbase + w_c4 * 4]);
            CP_COMMIT();
        }
    }

    const int row0 = wm * 16 + r;
#pragma unroll
    for (int j = 0; j < 8; j++) {
        const int col = colbase + wn * 64 + j * 8 + 2 * qd;
        *(float2*)&part[((size_t)kc * NUM_SEQS + row0) * HIDDEN + col] =
            make_float2(c[j].x, c[j].y);
        *(float2*)&part[((size_t)kc * NUM_SEQS + row0 + 8) * HIDDEN + col] =
            make_float2(c[j].z, c[j].w);
    }
}

// Reduce split-K partials + bias -> C[64, 2048]
__global__ __launch_bounds__(256)
void gemm_reduce_kernel(const float* __restrict__ part,
                        const float* __restrict__ bias,
                        float* __restrict__ C) {
    const int i = blockIdx.x * 256 + threadIdx.x;
    if (i >= NUM_SEQS * HIDDEN / 4) return;
    const int col4 = (i * 4) & (HIDDEN - 1);
    float4 s = *(const float4*)&bias[col4];
#pragma unroll
    for (int c = 0; c < KCHUNKS; c++) {
        const float4 p = *(const float4*)&part[(size_t)c * NUM_SEQS * HIDDEN + (size_t)i * 4];
        s.x += p.x; s.y += p.y; s.z += p.z; s.w += p.w;
    }
    *(float4*)&C[(size_t)i * 4] = s;
}

// ---------------------------------------------------------------------------
// Split-KV paged attention, partial pass (proven unroll-4 config; KV loads
// use streaming cache policy — single-use data, evict-first).
// ---------------------------------------------------------------------------
__global__ __launch_bounds__(128)
void attn_partial_kernel(const float* __restrict__ q,
                         const float* __restrict__ kv,
                         const int*   __restrict__ block_tables,
                         const int*   __restrict__ seq_lens,
                         float*  __restrict__ part_o,
                         float2* __restrict__ part_ml) {
    const int seq   = blockIdx.x;
    const int head  = blockIdx.y;
    const int split = blockIdx.z;
    const int tid   = threadIdx.x;
    const int warp  = tid >> 5;
    const int lane  = tid & 31;
    const int pidx  = (seq * NUM_HEADS + head) * SPLITS + split;

    __shared__ float s_scores[CHUNK_MAX];
    __shared__ int   s_bt[MAX_BLOCKS];
    __shared__ float s_red[4];
    __shared__ float s_acc[4][HEAD_DIM];

    const int sl    = seq_lens[seq];
    const int chunk = (sl + SPLITS - 1) / SPLITS;
    const int t0    = split * chunk;
    const int t1    = min(sl, t0 + chunk);
    const int n     = t1 - t0;

    if (n <= 0) {
        part_o[(size_t)pidx * HEAD_DIM + tid] = 0.0f;
        if (tid == 0) part_ml[pidx] = make_float2(-1e30f, 0.0f);
        return;
    }

    if (tid < MAX_BLOCKS)
        s_bt[tid] = block_tables[seq * MAX_BLOCKS + tid];
    __syncthreads();

    const float* K = kv;
    const float* V = kv + (size_t)NUM_KV_BLOCKS * BLOCK_SZ * HIDDEN;
    const size_t hoff = (size_t)head * HEAD_DIM + lane * 4;

    const float4 qf = *(const float4*)(q + (size_t)seq * HIDDEN + head * HEAD_DIM + lane * 4);

    // ---- Pass 1: scores, 4 tokens per warp per iteration ----
    float wmax = -1e30f;
    for (int tb = t0 + warp * 4; tb < t1; tb += 16) {
        float4 kf[4];
#pragma unroll
        for (int u = 0; u < 4; u++) {
            const int t = tb + u;
            if (t < t1) {
                const int phys = s_bt[t >> 6];
                kf[u] = ldcs4(K + ((size_t)phys * BLOCK_SZ + (t & 63)) * HIDDEN + hoff);
            } else {
                kf[u] = make_float4(0.f, 0.f, 0.f, 0.f);
            }
        }
        float d0 = kf[0].x * qf.x + kf[0].y * qf.y + kf[0].z * qf.z + kf[0].w * qf.w;
        float d1 = kf[1].x * qf.x + kf[1].y * qf.y + kf[1].z * qf.z + kf[1].w * qf.w;
        float d2 = kf[2].x * qf.x + kf[2].y * qf.y + kf[2].z * qf.z + kf[2].w * qf.w;
        float d3 = kf[3].x * qf.x + kf[3].y * qf.y + kf[3].z * qf.z + kf[3].w * qf.w;
#pragma unroll
        for (int o = 16; o; o >>= 1) {
            d0 += __shfl_xor_sync(0xffffffffu, d0, o);
            d1 += __shfl_xor_sync(0xffffffffu, d1, o);
            d2 += __shfl_xor_sync(0xffffffffu, d2, o);
            d3 += __shfl_xor_sync(0xffffffffu, d3, o);
        }
        d0 *= SCALE_F; d1 *= SCALE_F; d2 *= SCALE_F; d3 *= SCALE_F;
        if (lane == 0) {
            const int i = tb - t0;
            s_scores[i] = d0;
            if (tb + 1 < t1) s_scores[i + 1] = d1;
            if (tb + 2 < t1) s_scores[i + 2] = d2;
            if (tb + 3 < t1) s_scores[i + 3] = d3;
        }
        wmax = fmaxf(wmax, d0);
        if (tb + 1 < t1) wmax = fmaxf(wmax, d1);
        if (tb + 2 < t1) wmax = fmaxf(wmax, d2);
        if (tb + 3 < t1) wmax = fmaxf(wmax, d3);
    }
    if (lane == 0) s_red[warp] = wmax;
    __syncthreads();
    const float m = fmaxf(fmaxf(s_red[0], s_red[1]), fmaxf(s_red[2], s_red[3]));
    __syncthreads();

    // ---- Pass 2: exp + sum ----
    float lsum = 0.0f;
    for (int i = tid; i < n; i += 128) {
        float p = __expf(s_scores[i] - m);
        s_scores[i] = p;
        lsum += p;
    }
#pragma unroll
    for (int o = 16; o; o >>= 1)
        lsum += __shfl_xor_sync(0xffffffffu, lsum, o);
    if (lane == 0) s_red[warp] = lsum;
    __syncthreads();
    const float ltot = s_red[0] + s_red[1] + s_red[2] + s_red[3];

    // ---- Pass 3: weighted V, 4 tokens per warp per iteration ----
    float4 acc = make_float4(0.f, 0.f, 0.f, 0.f);
    for (int tb = t0 + warp * 4; tb < t1; tb += 16) {
        float4 vf[4];
        float  p[4];
#pragma unroll
        for (int u = 0; u < 4; u++) {
            const int t = tb + u;
            if (t < t1) {
                const int phys = s_bt[t >> 6];
                vf[u] = ldcs4(V + ((size_t)phys * BLOCK_SZ + (t & 63)) * HIDDEN + hoff);
                p[u]  = s_scores[t - t0];
            } else {
                vf[u] = make_float4(0.f, 0.f, 0.f, 0.f);
                p[u]  = 0.0f;
            }
        }
#pragma unroll
        for (int u = 0; u < 4; u++) {
            acc.x = fmaf(p[u], vf[u].x, acc.x);
            acc.y = fmaf(p[u], vf[u].y, acc.y);
            acc.z = fmaf(p[u], vf[u].z, acc.z);
            acc.w = fmaf(p[u], vf[u].w, acc.w);
        }
    }
    *(float4*)&s_acc[warp][lane * 4] = acc;
    __syncthreads();

    part_o[(size_t)pidx * HEAD_DIM + tid] =
        s_acc[0][tid] + s_acc[1][tid] + s_acc[2][tid] + s_acc[3][tid];
    if (tid == 0) part_ml[pidx] = make_float2(m, ltot);
}

// Combine SPLITS partials via log-sum-exp. grid (64*16), 128 threads.
__global__ __launch_bounds__(128)
void attn_combine_kernel(const float*  __restrict__ part_o,
                         const float2* __restrict__ part_ml,
                         float* __restrict__ out) {
    const int sh  = blockIdx.x;
    const int tid = threadIdx.x;

    float2 ml[SPLITS];
#pragma unroll
    for (int i = 0; i < SPLITS; i++) ml[i] = part_ml[sh * SPLITS + i];

    float M = -1e30f;
#pragma unroll
    for (int i = 0; i < SPLITS; i++) M = fmaxf(M, ml[i].x);

    float L = 0.0f, o = 0.0f;
#pragma unroll
    for (int i = 0; i < SPLITS; i++) {
        const float w = __expf(ml[i].x - M);
        L += w * ml[i].y;
        o = fmaf(w, part_o[(size_t)(sh * SPLITS + i) * HEAD_DIM + tid], o);
    }

    const int seq = sh >> 4, head = sh & 15;
    out[(size_t)seq * HIDDEN + head * HEAD_DIM + tid] = o / L;
}

// ---------------------------------------------------------------------------
extern "C" void kernel_launch(void* const* d_in, const int* in_sizes, int n_in,
                              void* d_out, int out_size) {
    const float* hs     = (const float*)d_in[0];
    const float* kv     = (const float*)d_in[1];
    const float* W_attn = (const float*)d_in[2];
    const float* b_attn = (const float*)d_in[3];
    const float* W_proj = (const float*)d_in[4];
    const float* b_proj = (const float*)d_in[5];
    const int*   bt     = (const int*)d_in[6];
    const int*   slen   = (const int*)d_in[7];
    float*       out    = (float*)d_out;

    float  *qp = nullptr, *ap = nullptr, *pp = nullptr, *po = nullptr;
    float2 *pml = nullptr;
    cudaGetSymbolAddress((void**)&qp,  g_q);
    cudaGetSymbolAddress((void**)&ap,  g_attn);
    cudaGetSymbolAddress((void**)&pp,  g_part);
    cudaGetSymbolAddress((void**)&po,  g_po);
    cudaGetSymbolAddress((void**)&pml, g_pml);

    cudaFuncSetAttribute(gemm_tc_kernel,
                         cudaFuncAttributeMaxDynamicSharedMemorySize,
                         GEMM_SMEM_BYTES);

    const dim3 gemm_grid(HIDDEN / 128, KCHUNKS);
    const int  red_ctas = (NUM_SEQS * HIDDEN / 4 + 255) / 256;

    // Q projection (only first HIDDEN cols of W_attn are used)
    gemm_tc_kernel<<<gemm_grid, 256, GEMM_SMEM_BYTES>>>(hs, W_attn, 3 * HIDDEN, pp);
    gemm_reduce_kernel<<<red_ctas, 256>>>(pp, b_attn, qp);

    // Paged attention, split-KV
    attn_partial_kernel<<<dim3(NUM_SEQS, NUM_HEADS, SPLITS), 128>>>(qp, kv, bt, slen, po, pml);
    attn_combine_kernel<<<NUM_SEQS * NUM_HEADS, 128>>>(po, pml, ap);

    // Output projection
    gemm_tc_kernel<<<gemm_grid, 256, GEMM_SMEM_BYTES>>>(ap, W_proj, HIDDEN, pp);
    gemm_reduce_kernel<<<red_ctas, 256>>>(pp, b_proj, out);
}

// round 14
// speedup vs baseline: 1.1657x; 1.0363x over previous
#include <cuda_runtime.h>
#include <math.h>

#define HIDDEN        2048
#define NUM_HEADS     16
#define HEAD_DIM      128
#define BLOCK_SZ      64
#define NUM_SEQS      64
#define MAX_SEQ_LEN   2048
#define MAX_BLOCKS    32
#define NUM_KV_BLOCKS 2048
#define SCALE_F       0.088388347648318447f   // 128^-0.5

#define KCHUNKS       16                       // GEMM split-K chunks
#define KCHUNK_SZ     (HIDDEN / KCHUNKS)       // 128
#define SPLITS        16                       // split-KV
#define CHUNK_MAX     (MAX_SEQ_LEN / SPLITS)   // 128

// GEMM tile: 64 seqs x 128 cols x 128 k per CTA; W pipelined in 32-row stages
#define APAD          132                      // fp32 row pitch (128 + 4)
#define WROWS         32                       // rows per W stage
#define GEMM_SMEM_BYTES ((64 * APAD + 2 * WROWS * APAD) * 4)   // 67584

// ---- static scratch (no allocations allowed) ----
__device__ float  g_q[NUM_SEQS * HIDDEN];
__device__ float  g_attn[NUM_SEQS * HIDDEN];
__device__ float  g_part[KCHUNKS * NUM_SEQS * HIDDEN];
__device__ float  g_po[NUM_SEQS * NUM_HEADS * SPLITS * HEAD_DIM];
__device__ float2 g_pml[NUM_SEQS * NUM_HEADS * SPLITS];

// ---- tf32 / cp.async helpers ----
__device__ __forceinline__ unsigned f2tf(float f) {
    unsigned r;
    asm("cvt.rna.tf32.f32 %0, %1;" : "=r"(r) : "f"(f));
    return r;
}
__device__ __forceinline__ void mma_tf32(float4& c,
                                         unsigned a0, unsigned a1, unsigned a2, unsigned a3,
                                         unsigned b0, unsigned b1) {
    asm("mma.sync.aligned.m16n8k8.row.col.f32.tf32.tf32.f32 "
        "{%0,%1,%2,%3}, {%4,%5,%6,%7}, {%8,%9}, {%0,%1,%2,%3};"
        : "+f"(c.x), "+f"(c.y), "+f"(c.z), "+f"(c.w)
        : "r"(a0), "r"(a1), "r"(a2), "r"(a3), "r"(b0), "r"(b1));
}
__device__ __forceinline__ unsigned smem_u32(const void* p) {
    return (unsigned)__cvta_generic_to_shared(p);
}
__device__ __forceinline__ void cp_async16(unsigned dst, const void* src) {
    asm volatile("cp.async.cg.shared.global [%0], [%1], 16;" :: "r"(dst), "l"(src));
}
#define CP_COMMIT()   asm volatile("cp.async.commit_group;" ::: "memory")
#define CP_WAIT(n)    asm volatile("cp.async.wait_group %0;" :: "n"(n) : "memory")

// streaming (evict-first) accessors for single-use data
__device__ __forceinline__ float4 ldcs4(const float* p) {
    float4 v;
    asm("ld.global.cs.v4.f32 {%0,%1,%2,%3}, [%4];"
        : "=f"(v.x), "=f"(v.y), "=f"(v.z), "=f"(v.w) : "l"(p));
    return v;
}
__device__ __forceinline__ float ldcs1(const float* p) {
    float v;
    asm("ld.global.cs.f32 %0, [%1];" : "=f"(v) : "l"(p));
    return v;
}
__device__ __forceinline__ void stcs2(float* p, float a, float b) {
    asm volatile("st.global.cs.v2.f32 [%0], {%1,%2};" :: "l"(p), "f"(a), "f"(b));
}
__device__ __forceinline__ void stcs1(float* p, float a) {
    asm volatile("st.global.cs.f32 [%0], %1;" :: "l"(p), "f"(a));
}

// ---------------------------------------------------------------------------
// Tensor-core split-K GEMM (tf32, cp.async pipelined) — proven R10 version,
// partials stored with streaming policy.
// ---------------------------------------------------------------------------
__global__ __launch_bounds__(256)
void gemm_tc_kernel(const float* __restrict__ A,
                    const float* __restrict__ W, int ldw,
                    float* __restrict__ part) {
    extern __shared__ float smemf[];
    float* Af = smemf;                     // [64][APAD]
    float* Wf = smemf + 64 * APAD;         // [2][WROWS][APAD]

    const int tid  = threadIdx.x;
    const int warp = tid >> 5;
    const int lane = tid & 31;
    const int r    = lane >> 2;
    const int qd   = lane & 3;
    const int wm   = warp >> 1;
    const int wn   = warp & 1;

    const int colbase = blockIdx.x * 128;
    const int kc      = blockIdx.y;
    const int kbeg    = kc * KCHUNK_SZ;

    const int a_row = tid >> 5, a_c4 = tid & 31;
    const int w_row = tid >> 5, w_c4 = tid & 31;

#pragma unroll
    for (int l = 0; l < 8; l++)
        cp_async16(smem_u32(&Af[(a_row + l * 8) * APAD + a_c4 * 4]),
                   &A[(size_t)(a_row + l * 8) * HIDDEN + kbeg + a_c4 * 4]);
#pragma unroll
    for (int l = 0; l < 4; l++)
        cp_async16(smem_u32(&Wf[(w_row + l * 8) * APAD + w_c4 * 4]),
                   &W[(size_t)(kbeg + w_row + l * 8) * ldw + colbase + w_c4 * 4]);
    CP_COMMIT();                                        // G0: A + W0
#pragma unroll
    for (int l = 0; l < 4; l++)
        cp_async16(smem_u32(&Wf[(WROWS + w_row + l * 8) * APAD + w_c4 * 4]),
                   &W[(size_t)(kbeg + WROWS + w_row + l * 8) * ldw + colbase + w_c4 * 4]);
    CP_COMMIT();                                        // G1: W1

    float4 c[8];
#pragma unroll
    for (int j = 0; j < 8; j++) c[j] = make_float4(0.f, 0.f, 0.f, 0.f);

    const float* arow0 = &Af[(wm * 16 + r) * APAD];
    const float* arow1 = &Af[(wm * 16 + r + 8) * APAD];
    const int nbase = wn * 64 + r;

#pragma unroll
    for (int kt = 0; kt < 4; kt++) {
        if (kt < 3) CP_WAIT(1); else CP_WAIT(0);
        __syncthreads();

        const float* wbuf = &Wf[(kt & 1) * WROWS * APAD];
        const int kofs = kt * WROWS;
#pragma unroll
        for (int ks = 0; ks < WROWS; ks += 8) {
            const unsigned a0 = f2tf(arow0[kofs + ks + qd]);
            const unsigned a1 = f2tf(arow1[kofs + ks + qd]);
            const unsigned a2 = f2tf(arow0[kofs + ks + qd + 4]);
            const unsigned a3 = f2tf(arow1[kofs + ks + qd + 4]);
            const float* w0 = &wbuf[(ks + qd) * APAD + nbase];
            const float* w1 = &wbuf[(ks + qd + 4) * APAD + nbase];
#pragma unroll
            for (int j = 0; j < 8; j++)
                mma_tf32(c[j], a0, a1, a2, a3, f2tf(w0[j * 8]), f2tf(w1[j * 8]));
        }

        if (kt + 2 < 4) {
            __syncthreads();
            const int s = kt + 2;
#pragma unroll
            for (int l = 0; l < 4; l++)
                cp_async16(smem_u32(&Wf[((kt & 1) * WROWS + w_row + l * 8) * APAD + w_c4 * 4]),
                           &W[(size_t)(kbeg + s * WROWS + w_row + l * 8) * ldw
                              + colbase + w_c4 * 4]);
            CP_COMMIT();
        }
    }

    const int row0 = wm * 16 + r;
#pragma unroll
    for (int j = 0; j < 8; j++) {
        const int col = colbase + wn * 64 + j * 8 + 2 * qd;
        stcs2(&part[((size_t)kc * NUM_SEQS + row0) * HIDDEN + col], c[j].x, c[j].y);
        stcs2(&part[((size_t)kc * NUM_SEQS + row0 + 8) * HIDDEN + col], c[j].z, c[j].w);
    }
}

// Reduce split-K partials + bias -> C[64, 2048]  (streaming reads)
__global__ __launch_bounds__(256)
void gemm_reduce_kernel(const float* __restrict__ part,
                        const float* __restrict__ bias,
                        float* __restrict__ C) {
    const int i = blockIdx.x * 256 + threadIdx.x;
    if (i >= NUM_SEQS * HIDDEN / 4) return;
    const int col4 = (i * 4) & (HIDDEN - 1);
    float4 s = *(const float4*)&bias[col4];
#pragma unroll
    for (int c = 0; c < KCHUNKS; c++) {
        const float4 p = ldcs4(&part[(size_t)c * NUM_SEQS * HIDDEN + (size_t)i * 4]);
        s.x += p.x; s.y += p.y; s.z += p.z; s.w += p.w;
    }
    *(float4*)&C[(size_t)i * 4] = s;
}

// ---------------------------------------------------------------------------
// Split-KV paged attention, partial pass (proven unroll-4 config; KV and
// partial-output streams use streaming cache policy).
// ---------------------------------------------------------------------------
__global__ __launch_bounds__(128)
void attn_partial_kernel(const float* __restrict__ q,
                         const float* __restrict__ kv,
                         const int*   __restrict__ block_tables,
                         const int*   __restrict__ seq_lens,
                         float*  __restrict__ part_o,
                         float2* __restrict__ part_ml) {
    const int seq   = blockIdx.x;
    const int head  = blockIdx.y;
    const int split = blockIdx.z;
    const int tid   = threadIdx.x;
    const int warp  = tid >> 5;
    const int lane  = tid & 31;
    const int pidx  = (seq * NUM_HEADS + head) * SPLITS + split;

    __shared__ float s_scores[CHUNK_MAX];
    __shared__ int   s_bt[MAX_BLOCKS];
    __shared__ float s_red[4];
    __shared__ float s_acc[4][HEAD_DIM];

    const int sl    = seq_lens[seq];
    const int chunk = (sl + SPLITS - 1) / SPLITS;
    const int t0    = split * chunk;
    const int t1    = min(sl, t0 + chunk);
    const int n     = t1 - t0;

    if (n <= 0) {
        stcs1(&part_o[(size_t)pidx * HEAD_DIM + tid], 0.0f);
        if (tid == 0) part_ml[pidx] = make_float2(-1e30f, 0.0f);
        return;
    }

    if (tid < MAX_BLOCKS)
        s_bt[tid] = block_tables[seq * MAX_BLOCKS + tid];
    __syncthreads();

    const float* K = kv;
    const float* V = kv + (size_t)NUM_KV_BLOCKS * BLOCK_SZ * HIDDEN;
    const size_t hoff = (size_t)head * HEAD_DIM + lane * 4;

    const float4 qf = *(const float4*)(q + (size_t)seq * HIDDEN + head * HEAD_DIM + lane * 4);

    // ---- Pass 1: scores, 4 tokens per warp per iteration ----
    float wmax = -1e30f;
    for (int tb = t0 + warp * 4; tb < t1; tb += 16) {
        float4 kf[4];
#pragma unroll
        for (int u = 0; u < 4; u++) {
            const int t = tb + u;
            if (t < t1) {
                const int phys = s_bt[t >> 6];
                kf[u] = ldcs4(K + ((size_t)phys * BLOCK_SZ + (t & 63)) * HIDDEN + hoff);
            } else {
                kf[u] = make_float4(0.f, 0.f, 0.f, 0.f);
            }
        }
        float d0 = kf[0].x * qf.x + kf[0].y * qf.y + kf[0].z * qf.z + kf[0].w * qf.w;
        float d1 = kf[1].x * qf.x + kf[1].y * qf.y + kf[1].z * qf.z + kf[1].w * qf.w;
        float d2 = kf[2].x * qf.x + kf[2].y * qf.y + kf[2].z * qf.z + kf[2].w * qf.w;
        float d3 = kf[3].x * qf.x + kf[3].y * qf.y + kf[3].z * qf.z + kf[3].w * qf.w;
#pragma unroll
        for (int o = 16; o; o >>= 1) {
            d0 += __shfl_xor_sync(0xffffffffu, d0, o);
            d1 += __shfl_xor_sync(0xffffffffu, d1, o);
            d2 += __shfl_xor_sync(0xffffffffu, d2, o);
            d3 += __shfl_xor_sync(0xffffffffu, d3, o);
        }
        d0 *= SCALE_F; d1 *= SCALE_F; d2 *= SCALE_F; d3 *= SCALE_F;
        if (lane == 0) {
            const int i = tb - t0;
            s_scores[i] = d0;
            if (tb + 1 < t1) s_scores[i + 1] = d1;
            if (tb + 2 < t1) s_scores[i + 2] = d2;
            if (tb + 3 < t1) s_scores[i + 3] = d3;
        }
        wmax = fmaxf(wmax, d0);
        if (tb + 1 < t1) wmax = fmaxf(wmax, d1);
        if (tb + 2 < t1) wmax = fmaxf(wmax, d2);
        if (tb + 3 < t1) wmax = fmaxf(wmax, d3);
    }
    if (lane == 0) s_red[warp] = wmax;
    __syncthreads();
    const float m = fmaxf(fmaxf(s_red[0], s_red[1]), fmaxf(s_red[2], s_red[3]));
    __syncthreads();

    // ---- Pass 2: exp + sum ----
    float lsum = 0.0f;
    for (int i = tid; i < n; i += 128) {
        float p = __expf(s_scores[i] - m);
        s_scores[i] = p;
        lsum += p;
    }
#pragma unroll
    for (int o = 16; o; o >>= 1)
        lsum += __shfl_xor_sync(0xffffffffu, lsum, o);
    if (lane == 0) s_red[warp] = lsum;
    __syncthreads();
    const float ltot = s_red[0] + s_red[1] + s_red[2] + s_red[3];

    // ---- Pass 3: weighted V, 4 tokens per warp per iteration ----
    float4 acc = make_float4(0.f, 0.f, 0.f, 0.f);
    for (int tb = t0 + warp * 4; tb < t1; tb += 16) {
        float4 vf[4];
        float  p[4];
#pragma unroll
        for (int u = 0; u < 4; u++) {
            const int t = tb + u;
            if (t < t1) {
                const int phys = s_bt[t >> 6];
                vf[u] = ldcs4(V + ((size_t)phys * BLOCK_SZ + (t & 63)) * HIDDEN + hoff);
                p[u]  = s_scores[t - t0];
            } else {
                vf[u] = make_float4(0.f, 0.f, 0.f, 0.f);
                p[u]  = 0.0f;
            }
        }
#pragma unroll
        for (int u = 0; u < 4; u++) {
            acc.x = fmaf(p[u], vf[u].x, acc.x);
            acc.y = fmaf(p[u], vf[u].y, acc.y);
            acc.z = fmaf(p[u], vf[u].z, acc.z);
            acc.w = fmaf(p[u], vf[u].w, acc.w);
        }
    }
    *(float4*)&s_acc[warp][lane * 4] = acc;
    __syncthreads();

    stcs1(&part_o[(size_t)pidx * HEAD_DIM + tid],
          s_acc[0][tid] + s_acc[1][tid] + s_acc[2][tid] + s_acc[3][tid]);
    if (tid == 0) part_ml[pidx] = make_float2(m, ltot);
}

// Combine SPLITS partials via log-sum-exp. grid (64*16), 128 threads.
__global__ __launch_bounds__(128)
void attn_combine_kernel(const float*  __restrict__ part_o,
                         const float2* __restrict__ part_ml,
                         float* __restrict__ out) {
    const int sh  = blockIdx.x;
    const int tid = threadIdx.x;

    float2 ml[SPLITS];
#pragma unroll
    for (int i = 0; i < SPLITS; i++) ml[i] = part_ml[sh * SPLITS + i];

    float M = -1e30f;
#pragma unroll
    for (int i = 0; i < SPLITS; i++) M = fmaxf(M, ml[i].x);

    float L = 0.0f, o = 0.0f;
#pragma unroll
    for (int i = 0; i < SPLITS; i++) {
        const float w = __expf(ml[i].x - M);
        L += w * ml[i].y;
        o = fmaf(w, ldcs1(&part_o[(size_t)(sh * SPLITS + i) * HEAD_DIM + tid]), o);
    }

    const int seq = sh >> 4, head = sh & 15;
    out[(size_t)seq * HIDDEN + head * HEAD_DIM + tid] = o / L;
}

// ---------------------------------------------------------------------------
extern "C" void kernel_launch(void* const* d_in, const int* in_sizes, int n_in,
                              void* d_out, int out_size) {
    const float* hs     = (const float*)d_in[0];
    const float* kv     = (const float*)d_in[1];
    const float* W_attn = (const float*)d_in[2];
    const float* b_attn = (const float*)d_in[3];
    const float* W_proj = (const float*)d_in[4];
    const float* b_proj = (const float*)d_in[5];
    const int*   bt     = (const int*)d_in[6];
    const int*   slen   = (const int*)d_in[7];
    float*       out    = (float*)d_out;

    float  *qp = nullptr, *ap = nullptr, *pp = nullptr, *po = nullptr;
    float2 *pml = nullptr;
    cudaGetSymbolAddress((void**)&qp,  g_q);
    cudaGetSymbolAddress((void**)&ap,  g_attn);
    cudaGetSymbolAddress((void**)&pp,  g_part);
    cudaGetSymbolAddress((void**)&po,  g_po);
    cudaGetSymbolAddress((void**)&pml, g_pml);

    cudaFuncSetAttribute(gemm_tc_kernel,
                         cudaFuncAttributeMaxDynamicSharedMemorySize,
                         GEMM_SMEM_BYTES);

    const dim3 gemm_grid(HIDDEN / 128, KCHUNKS);
    const int  red_ctas = (NUM_SEQS * HIDDEN / 4 + 255) / 256;

    // Q projection (only first HIDDEN cols of W_attn are used)
    gemm_tc_kernel<<<gemm_grid, 256, GEMM_SMEM_BYTES>>>(hs, W_attn, 3 * HIDDEN, pp);
    gemm_reduce_kernel<<<red_ctas, 256>>>(pp, b_attn, qp);

    // Paged attention, split-KV
    attn_partial_kernel<<<dim3(NUM_SEQS, NUM_HEADS, SPLITS), 128>>>(qp, kv, bt, slen, po, pml);
    attn_combine_kernel<<<NUM_SEQS * NUM_HEADS, 128>>>(po, pml, ap);

    // Output projection
    gemm_tc_kernel<<<gemm_grid, 256, GEMM_SMEM_BYTES>>>(ap, W_proj, HIDDEN, pp);
    gemm_reduce_kernel<<<red_ctas, 256>>>(pp, b_proj, out);
}